// round 4
// baseline (speedup 1.0000x reference)
#include <cuda_runtime.h>
#include <cuda_bf16.h>
#include <cstdint>
#include <math.h>

// ---------------- problem constants ----------------
#define BB   32
#define WN   64
#define NT   50
#define CC   384
#define NH   12
#define DD   32
#define WS   7
#define HW   3136
#define SCALE 0.17677669529663687f

#define M1 (BB*WN*NT)   // 102400
#define M2 (BB*WN)      // 2048
#define M3 (BB*HW)      // 100352

// ---------------- device scratch ----------------
__device__ float g_qkv  [(size_t)M1*3*CC];
__device__ float g_out1 [(size_t)M1*CC];
__device__ float g_pqk  [(size_t)M2*2*CC];
__device__ float g_pattn[(size_t)BB*NH*WN*WN];

__device__ __nv_bfloat16 g_x_hi[(size_t)M1*CC],  g_x_lo[(size_t)M1*CC];
__device__ __nv_bfloat16 g_wqkv_hi[3*CC*CC],     g_wqkv_lo[3*CC*CC];
__device__ __nv_bfloat16 g_wqk_hi [2*CC*CC],     g_wqk_lo [2*CC*CC];
__device__ __nv_bfloat16 g_wproj_hi[CC*CC],      g_wproj_lo[CC*CC];
__device__ __nv_bfloat16 g_wt_hi[(size_t)M2*CC], g_wt_lo[(size_t)M2*CC];
__device__ __nv_bfloat16 g_fin_hi[(size_t)M3*CC],g_fin_lo[(size_t)M3*CC];

// ---------------- PTX helpers (baseline ISA only) ----------------
__device__ __forceinline__ uint32_t smem_u32(const void* p) {
    uint32_t r;
    asm("{ .reg .u64 t; cvta.to.shared.u64 t, %1; cvt.u32.u64 %0, t; }" : "=r"(r) : "l"(p));
    return r;
}
__device__ __forceinline__ void cpa16(uint32_t s, const void* g) {
    asm volatile("cp.async.cg.shared.global [%0], [%1], 16;" :: "r"(s), "l"(g));
}
__device__ __forceinline__ void cpa_commit() {
    asm volatile("cp.async.commit_group;" ::: "memory");
}
template<int N>
__device__ __forceinline__ void cpa_wait() {
    asm volatile("cp.async.wait_group %0;" :: "n"(N) : "memory");
}
__device__ __forceinline__ void ldsm_x4(uint32_t& r0, uint32_t& r1, uint32_t& r2, uint32_t& r3,
                                        uint32_t a) {
    asm volatile("ldmatrix.sync.aligned.m8n8.x4.shared.b16 {%0,%1,%2,%3}, [%4];"
                 : "=r"(r0), "=r"(r1), "=r"(r2), "=r"(r3) : "r"(a));
}
__device__ __forceinline__ void ldsm_x2(uint32_t& r0, uint32_t& r1, uint32_t a) {
    asm volatile("ldmatrix.sync.aligned.m8n8.x2.shared.b16 {%0,%1}, [%2];"
                 : "=r"(r0), "=r"(r1) : "r"(a));
}
__device__ __forceinline__ void mma_bf16(float* d, const uint32_t* a, const uint32_t* b) {
    asm volatile(
        "mma.sync.aligned.m16n8k16.row.col.f32.bf16.bf16.f32 "
        "{%0,%1,%2,%3}, {%4,%5,%6,%7}, {%8,%9}, {%0,%1,%2,%3};"
        : "+f"(d[0]), "+f"(d[1]), "+f"(d[2]), "+f"(d[3])
        : "r"(a[0]), "r"(a[1]), "r"(a[2]), "r"(a[3]), "r"(b[0]), "r"(b[1]));
}

// ---------------- bf16 hi/lo split ----------------
__global__ void split_kernel(const float4* __restrict__ in,
                             __nv_bfloat16* __restrict__ hi,
                             __nv_bfloat16* __restrict__ lo, int n4)
{
    int i = blockIdx.x * 256 + threadIdx.x;
    if (i >= n4) return;
    float4 v = in[i];
    float xs[4] = {v.x, v.y, v.z, v.w};
    union { __nv_bfloat16 b[4]; uint2 u; } H, L;
    #pragma unroll
    for (int j = 0; j < 4; j++) {
        __nv_bfloat16 h = __float2bfloat16(xs[j]);
        H.b[j] = h;
        L.b[j] = __float2bfloat16(xs[j] - __bfloat162float(h));
    }
    *reinterpret_cast<uint2*>(hi + (size_t)i * 4) = H.u;
    *reinterpret_cast<uint2*>(lo + (size_t)i * 4) = L.u;
}

// ---------------- bf16x3 HMMA GEMM (unchanged from R3) ----------------
#define BKH   32
#define PITCH 80
#define PLANE (128 * PITCH)
#define BUF_B (4 * PLANE)
#define SMEM_TOT (2 * BUF_B)

__device__ __forceinline__ void load_plane(uint32_t dst, const __nv_bfloat16* __restrict__ G,
                                           int row0, int k0, int K, int tid)
{
    #pragma unroll
    for (int i = 0; i < 2; i++) {
        int seg = tid + i * 256;
        int r = seg >> 2, u = seg & 3;
        cpa16(dst + r * PITCH + u * 16, G + (size_t)(row0 + r) * K + k0 + u * 8);
    }
}

__global__ void __launch_bounds__(256, 1)
mma_gemm(const __nv_bfloat16* __restrict__ Ahi, const __nv_bfloat16* __restrict__ Alo,
         const __nv_bfloat16* __restrict__ Bhi, const __nv_bfloat16* __restrict__ Blo,
         const float* __restrict__ bias, float* __restrict__ C, int N, int K)
{
    extern __shared__ __align__(128) char dsm[];
    const int tid  = threadIdx.x;
    const int lane = tid & 31;
    const int wid  = tid >> 5;
    const int wm   = wid & 1;
    const int wn   = wid >> 1;
    const int m0 = blockIdx.y * 128;
    const int n0 = blockIdx.x * 128;
    const uint32_t sb = smem_u32(dsm);

    float acc[4][4][4];
    #pragma unroll
    for (int mi = 0; mi < 4; mi++)
        #pragma unroll
        for (int ni = 0; ni < 4; ni++)
            #pragma unroll
            for (int f = 0; f < 4; f++) acc[mi][ni][f] = 0.f;

    const int NC = K / BKH;

    {
        uint32_t buf = sb;
        load_plane(buf + 0 * PLANE, Ahi, m0, 0, K, tid);
        load_plane(buf + 1 * PLANE, Alo, m0, 0, K, tid);
        load_plane(buf + 2 * PLANE, Bhi, n0, 0, K, tid);
        load_plane(buf + 3 * PLANE, Blo, n0, 0, K, tid);
        cpa_commit();
    }

    const int l16 = lane & 15;
    const uint32_t a_row = wm * 64 + l16;
    const uint32_t a_cb  = ((lane >> 4) & 1) * 16;
    const uint32_t b_row = wn * 32 + (l16 & 7);
    const uint32_t b_cb  = (l16 >> 3) * 16;

    for (int c = 0; c < NC; c++) {
        if (c + 1 < NC) {
            uint32_t buf = sb + ((c + 1) & 1) * BUF_B;
            load_plane(buf + 0 * PLANE, Ahi, m0, (c + 1) * BKH, K, tid);
            load_plane(buf + 1 * PLANE, Alo, m0, (c + 1) * BKH, K, tid);
            load_plane(buf + 2 * PLANE, Bhi, n0, (c + 1) * BKH, K, tid);
            load_plane(buf + 3 * PLANE, Blo, n0, (c + 1) * BKH, K, tid);
            cpa_commit();
            cpa_wait<1>();
        } else {
            cpa_wait<0>();
        }
        __syncthreads();

        const uint32_t buf = sb + (c & 1) * BUF_B;
        #pragma unroll
        for (int ks = 0; ks < 2; ks++) {
            uint32_t ah[4][4], al[4][4], bh[4][2], bl[4][2];
            #pragma unroll
            for (int mi = 0; mi < 4; mi++) {
                uint32_t off = (a_row + mi * 16) * PITCH + ks * 32 + a_cb;
                ldsm_x4(ah[mi][0], ah[mi][1], ah[mi][2], ah[mi][3], buf + 0 * PLANE + off);
                ldsm_x4(al[mi][0], al[mi][1], al[mi][2], al[mi][3], buf + 1 * PLANE + off);
            }
            #pragma unroll
            for (int ni = 0; ni < 4; ni++) {
                uint32_t off = (b_row + ni * 8) * PITCH + ks * 32 + b_cb;
                ldsm_x2(bh[ni][0], bh[ni][1], buf + 2 * PLANE + off);
                ldsm_x2(bl[ni][0], bl[ni][1], buf + 3 * PLANE + off);
            }
            #pragma unroll
            for (int mi = 0; mi < 4; mi++)
                #pragma unroll
                for (int ni = 0; ni < 4; ni++) {
                    mma_bf16(acc[mi][ni], ah[mi], bh[ni]);
                    mma_bf16(acc[mi][ni], ah[mi], bl[ni]);
                    mma_bf16(acc[mi][ni], al[mi], bh[ni]);
                }
        }
        __syncthreads();
    }

    const int rr = lane >> 2, cp = (lane & 3) * 2;
    #pragma unroll
    for (int mi = 0; mi < 4; mi++) {
        int row = m0 + wm * 64 + mi * 16 + rr;
        #pragma unroll
        for (int ni = 0; ni < 4; ni++) {
            int col = n0 + wn * 32 + ni * 8 + cp;
            float b0 = 0.f, b1 = 0.f;
            if (bias) { b0 = bias[col]; b1 = bias[col + 1]; }
            float* p = C + (size_t)row * N + col;
            p[0] = acc[mi][ni][0] + b0;
            p[1] = acc[mi][ni][1] + b1;
            float* q = p + (size_t)8 * N;
            q[0] = acc[mi][ni][2] + b0;
            q[1] = acc[mi][ni][3] + b1;
        }
    }
}

// ---------------- K2 v2: register-tiled window attention + residual ----------
// Pitch 36 floats (144B, 16B-aligned, conflict-free float4 across rows).
#define QKP 36
__global__ void __launch_bounds__(256)
win_attn_kernel(const float* __restrict__ qkv,
                const float* __restrict__ x,
                float* __restrict__ out1)
{
    const int bw = blockIdx.x;
    const int hh = blockIdx.y;
    __shared__ __align__(16) float q[NT][QKP];
    __shared__ __align__(16) float k[NT][QKP];
    __shared__ __align__(16) float v[NT][QKP];
    __shared__ __align__(16) float at[NT][52];
    const int tid  = threadIdx.x;
    const int warp = tid >> 5, lane = tid & 31;

    // load q,k,v (50 rows x 32 floats each) as float4
    {
        const float* base = qkv + (size_t)bw * NT * (3 * CC) + hh * DD;
        for (int seg = tid; seg < NT * 24; seg += 256) {
            int i = seg / 24, r = seg % 24;
            int t = r >> 3, u = r & 7;            // tensor 0..2, float4 0..7
            float4 val = *reinterpret_cast<const float4*>(base + (size_t)i * (3 * CC) + t * CC + u * 4);
            float* dst = (t == 0 ? &q[i][u * 4] : t == 1 ? &k[i][u * 4] : &v[i][u * 4]);
            *reinterpret_cast<float4*>(dst) = val;
        }
    }
    __syncthreads();

    // scores: warp handles 4 rows, lanes = column j (2 passes)
    for (int ig = warp; ig < 13; ig += 8) {
        const int i0 = ig * 4;
        #pragma unroll
        for (int jp = 0; jp < 2; jp++) {
            int j = jp * 32 + lane;
            if (j < NT) {
                float acc[4] = {0.f, 0.f, 0.f, 0.f};
                #pragma unroll
                for (int u = 0; u < 8; u++) {
                    float4 kv = *reinterpret_cast<const float4*>(&k[j][u * 4]);
                    #pragma unroll
                    for (int r = 0; r < 4; r++) {
                        int i = i0 + r; if (i > 49) i = 49;
                        float4 qv = *reinterpret_cast<const float4*>(&q[i][u * 4]);
                        acc[r] += qv.x * kv.x + qv.y * kv.y + qv.z * kv.z + qv.w * kv.w;
                    }
                }
                #pragma unroll
                for (int r = 0; r < 4; r++)
                    if (i0 + r < NT) at[i0 + r][j] = acc[r] * SCALE;
            }
        }
    }
    __syncthreads();

    // softmax: warp per row, shuffle reductions
    for (int i = warp; i < NT; i += 8) {
        float a0 = at[i][lane];
        float a1 = (lane < 18) ? at[i][32 + lane] : -1e30f;
        float m = fmaxf(a0, a1);
        #pragma unroll
        for (int o = 16; o; o >>= 1) m = fmaxf(m, __shfl_xor_sync(0xFFFFFFFFu, m, o));
        float e0 = __expf(a0 - m);
        float e1 = (lane < 18) ? __expf(a1 - m) : 0.f;
        float s = e0 + e1;
        #pragma unroll
        for (int o = 16; o; o >>= 1) s += __shfl_xor_sync(0xFFFFFFFFu, s, o);
        float inv = 1.f / s;
        at[i][lane] = e0 * inv;
        if (lane < 18) at[i][32 + lane] = e1 * inv;
    }
    __syncthreads();

    // AV: warp handles 4 rows, lanes = dd
    for (int ig = warp; ig < 13; ig += 8) {
        const int i0 = ig * 4;
        const int dd = lane;
        float acc[4] = {0.f, 0.f, 0.f, 0.f};
        #pragma unroll
        for (int j4 = 0; j4 < 48; j4 += 4) {
            float v0 = v[j4 + 0][dd], v1 = v[j4 + 1][dd];
            float v2 = v[j4 + 2][dd], v3 = v[j4 + 3][dd];
            #pragma unroll
            for (int r = 0; r < 4; r++) {
                int i = i0 + r; if (i > 49) i = 49;
                float4 a = *reinterpret_cast<const float4*>(&at[i][j4]);
                acc[r] += a.x * v0 + a.y * v1 + a.z * v2 + a.w * v3;
            }
        }
        {
            float v0 = v[48][dd], v1 = v[49][dd];
            #pragma unroll
            for (int r = 0; r < 4; r++) {
                int i = i0 + r; if (i > 49) i = 49;
                acc[r] += at[i][48] * v0 + at[i][49] * v1;
            }
        }
        #pragma unroll
        for (int r = 0; r < 4; r++) {
            int i = i0 + r;
            if (i < NT) {
                size_t o = (size_t)bw * NT * CC + (size_t)i * CC + hh * DD + dd;
                out1[o] = acc[r] + x[o];
            }
        }
    }
}

// ---------------- K3a: LayerNorm + exact GELU -> bf16 hi/lo -----------------
__global__ void ln_gelu_kernel(const float* __restrict__ out1,
                               const float* __restrict__ g,
                               const float* __restrict__ b,
                               __nv_bfloat16* __restrict__ wt_hi,
                               __nv_bfloat16* __restrict__ wt_lo)
{
    const int bw = blockIdx.x;
    const int tid = threadIdx.x; // 128
    const float* row = out1 + (size_t)bw * NT * CC;
    float vv[3], s = 0.f, s2 = 0.f;
    #pragma unroll
    for (int i = 0; i < 3; i++) {
        vv[i] = row[tid + i * 128];
        s += vv[i]; s2 += vv[i] * vv[i];
    }
    __shared__ float rs[4], rs2[4];
    #pragma unroll
    for (int o = 16; o; o >>= 1) {
        s  += __shfl_down_sync(0xFFFFFFFFu, s,  o);
        s2 += __shfl_down_sync(0xFFFFFFFFu, s2, o);
    }
    if ((tid & 31) == 0) { rs[tid >> 5] = s; rs2[tid >> 5] = s2; }
    __syncthreads();
    float S  = rs[0] + rs[1] + rs[2] + rs[3];
    float S2 = rs2[0] + rs2[1] + rs2[2] + rs2[3];
    float mean = S / (float)CC;
    float var  = S2 / (float)CC - mean * mean;
    float inv  = rsqrtf(var + 1e-5f);
    #pragma unroll
    for (int i = 0; i < 3; i++) {
        int c = tid + i * 128;
        float nz = (vv[i] - mean) * inv * g[c] + b[c];
        float ge = 0.5f * nz * (1.f + erff(nz * 0.70710678118654752f));
        __nv_bfloat16 h = __float2bfloat16(ge);
        wt_hi[(size_t)bw * CC + c] = h;
        wt_lo[(size_t)bw * CC + c] = __float2bfloat16(ge - __bfloat162float(h));
    }
}

// ---------------- K4: pooled attention softmax ------------------------------
__global__ void pool_attn_kernel(const float* __restrict__ pqk,
                                 float* __restrict__ pattn)
{
    const int b = blockIdx.x, hh = blockIdx.y;
    __shared__ float pq[WN][32];
    __shared__ float pk[WN][33];
    __shared__ float sc[WN][WN];
    const int tid = threadIdx.x; // 256

    for (int idx = tid; idx < WN * 32; idx += 256) {
        int w = idx >> 5, d = idx & 31;
        size_t base = (size_t)(b * WN + w) * (2 * CC) + hh * DD + d;
        pq[w][d] = pqk[base];
        pk[w][d] = pqk[base + CC];
    }
    __syncthreads();

    for (int idx = tid; idx < WN * WN; idx += 256) {
        int w = idx >> 6, vv = idx & 63;
        float s = 0.f;
        #pragma unroll
        for (int d = 0; d < 32; d++) s += pq[w][d] * pk[vv][d];
        sc[w][vv] = s * SCALE;
    }
    __syncthreads();

    if (tid < WN) {
        float m = -1e30f;
        for (int j = 0; j < WN; j++) m = fmaxf(m, sc[tid][j]);
        float sum = 0.f;
        for (int j = 0; j < WN; j++) { float e = __expf(sc[tid][j] - m); sc[tid][j] = e; sum += e; }
        float inv = 1.f / sum;
        for (int j = 0; j < WN; j++) sc[tid][j] *= inv;
    }
    __syncthreads();

    float* dst = pattn + (size_t)(b * NH + hh) * WN * WN;
    for (int idx = tid; idx < WN * WN; idx += 256) dst[idx] = sc[idx >> 6][idx & 63];
}

// ---------------- K5 v2: PSA mix + residual + rearrange -> bf16 hi/lo -------
// bv[] (the 64 windows' values for this (s,col)) held in registers; doubles
// as the residual. Per-w dot via float4 broadcast LDS.
__global__ void __launch_bounds__(224)
psa_kernel(const float* __restrict__ pattn,
           const float* __restrict__ out1,
           __nv_bfloat16* __restrict__ fin_hi,
           __nv_bfloat16* __restrict__ fin_lo)
{
    const int bh = blockIdx.x;
    const int b = bh / NH, hh = bh % NH;
    const int si = blockIdx.y;
    __shared__ __align__(16) float sp[WN][WN];
    const int tid = threadIdx.x; // 224

    const float* src = pattn + (size_t)bh * WN * WN;
    for (int idx = tid; idx < WN * WN; idx += 224) sp[idx >> 6][idx & 63] = src[idx];
    __syncthreads();

    const int sj = tid >> 5, dd = tid & 31;
    const int s = si * 7 + sj;
    const int col = hh * DD + dd;

    float bv[WN];
    {
        const float* p = out1 + ((size_t)b * WN * NT + s + 1) * CC + col;
        #pragma unroll
        for (int w = 0; w < WN; w++) bv[w] = p[(size_t)w * NT * CC];
    }

    for (int w = 0; w < WN; w++) {
        float acc = 0.f;
        #pragma unroll
        for (int v4 = 0; v4 < 16; v4++) {
            float4 pv = *reinterpret_cast<const float4*>(&sp[w][v4 * 4]);
            acc += pv.x * bv[v4 * 4] + pv.y * bv[v4 * 4 + 1]
                 + pv.z * bv[v4 * 4 + 2] + pv.w * bv[v4 * 4 + 3];
        }
        float f = acc + bv[w];
        int hi = w >> 3, wi = w & 7;
        int y = hi * WS + si, xx = wi * WS + sj;
        size_t o = ((size_t)b * HW + y * 56 + xx) * CC + col;
        __nv_bfloat16 h = __float2bfloat16(f);
        fin_hi[o] = h;
        fin_lo[o] = __float2bfloat16(f - __bfloat162float(h));
    }
}

// ---------------- launch ----------------
extern "C" void kernel_launch(void* const* d_in, const int* in_sizes, int n_in,
                              void* d_out, int out_size)
{
    const float* x      = (const float*)d_in[0];
    const float* w_qkv  = (const float*)d_in[3];
    const float* w_qk   = (const float*)d_in[4];
    const float* ln_g   = (const float*)d_in[5];
    const float* ln_b   = (const float*)d_in[6];
    const float* w_proj = (const float*)d_in[7];
    const float* b_proj = (const float*)d_in[8];
    float* out = (float*)d_out;

    float *p_qkv, *p_out1, *p_pqk, *p_pattn;
    __nv_bfloat16 *p_xh, *p_xl, *p_wqkvh, *p_wqkvl, *p_wqkh, *p_wqkl,
                  *p_wprojh, *p_wprojl, *p_wth, *p_wtl, *p_finh, *p_finl;
    cudaGetSymbolAddress((void**)&p_qkv,   g_qkv);
    cudaGetSymbolAddress((void**)&p_out1,  g_out1);
    cudaGetSymbolAddress((void**)&p_pqk,   g_pqk);
    cudaGetSymbolAddress((void**)&p_pattn, g_pattn);
    cudaGetSymbolAddress((void**)&p_xh,    g_x_hi);
    cudaGetSymbolAddress((void**)&p_xl,    g_x_lo);
    cudaGetSymbolAddress((void**)&p_wqkvh, g_wqkv_hi);
    cudaGetSymbolAddress((void**)&p_wqkvl, g_wqkv_lo);
    cudaGetSymbolAddress((void**)&p_wqkh,  g_wqk_hi);
    cudaGetSymbolAddress((void**)&p_wqkl,  g_wqk_lo);
    cudaGetSymbolAddress((void**)&p_wprojh,g_wproj_hi);
    cudaGetSymbolAddress((void**)&p_wprojl,g_wproj_lo);
    cudaGetSymbolAddress((void**)&p_wth,   g_wt_hi);
    cudaGetSymbolAddress((void**)&p_wtl,   g_wt_lo);
    cudaGetSymbolAddress((void**)&p_finh,  g_fin_hi);
    cudaGetSymbolAddress((void**)&p_finl,  g_fin_lo);

    cudaFuncSetAttribute(mma_gemm, cudaFuncAttributeMaxDynamicSharedMemorySize, SMEM_TOT);

    // splits
    {
        int n4 = (M1 * CC) / 4;
        split_kernel<<<(n4 + 255) / 256, 256>>>((const float4*)x, p_xh, p_xl, n4);
        n4 = (3 * CC * CC) / 4;
        split_kernel<<<(n4 + 255) / 256, 256>>>((const float4*)w_qkv, p_wqkvh, p_wqkvl, n4);
        n4 = (2 * CC * CC) / 4;
        split_kernel<<<(n4 + 255) / 256, 256>>>((const float4*)w_qk, p_wqkh, p_wqkl, n4);
        n4 = (CC * CC) / 4;
        split_kernel<<<(n4 + 255) / 256, 256>>>((const float4*)w_proj, p_wprojh, p_wprojl, n4);
    }

    // K1: qkv = x @ w_qkv^T  (102400 x 1152, K=384)
    mma_gemm<<<dim3(3 * CC / 128, M1 / 128), 256, SMEM_TOT>>>(
        p_xh, p_xl, p_wqkvh, p_wqkvl, nullptr, p_qkv, 3 * CC, CC);

    // K2: window attention + residual
    win_attn_kernel<<<dim3(BB * WN, NH), 256>>>(p_qkv, x, p_out1);

    // K3a: LN + GELU -> bf16 hi/lo
    ln_gelu_kernel<<<M2, 128>>>(p_out1, ln_g, ln_b, p_wth, p_wtl);

    // K3b: pqk = wintok @ w_qk^T  (2048 x 768, K=384)
    mma_gemm<<<dim3(2 * CC / 128, M2 / 128), 256, SMEM_TOT>>>(
        p_wth, p_wtl, p_wqkh, p_wqkl, nullptr, p_pqk, 2 * CC, CC);

    // K4: pooled attention softmax
    pool_attn_kernel<<<dim3(BB, NH), 256>>>(p_pqk, p_pattn);

    // K5: PSA mix + residual + rearrange -> bf16 hi/lo
    psa_kernel<<<dim3(BB * NH, WS), 224>>>(p_pattn, p_out1, p_finh, p_finl);

    // K6: out = final @ w_proj^T + b_proj  (100352 x 384, K=384)
    mma_gemm<<<dim3(CC / 128, M3 / 128), 256, SMEM_TOT>>>(
        p_finh, p_finl, p_wprojh, p_wprojl, b_proj, out, CC, CC);
}

// round 6
// speedup vs baseline: 1.1513x; 1.1513x over previous
#include <cuda_runtime.h>
#include <cuda_bf16.h>
#include <cstdint>
#include <math.h>

// ---------------- problem constants ----------------
#define BB   32
#define WN   64
#define NT   50
#define CC   384
#define NH   12
#define DD   32
#define WS   7
#define HW   3136
#define SCALE 0.17677669529663687f

#define M1 (BB*WN*NT)   // 102400
#define M2 (BB*WN)      // 2048
#define M3 (BB*HW)      // 100352

// ---------------- device scratch ----------------
__device__ float g_qkv  [(size_t)M1*3*CC];
__device__ float g_out1 [(size_t)M1*CC];
__device__ float g_pqk  [(size_t)M2*2*CC];
__device__ float g_pattn[(size_t)BB*NH*WN*WN];

__device__ __nv_bfloat16 g_x_hi[(size_t)M1*CC],  g_x_lo[(size_t)M1*CC];
__device__ __nv_bfloat16 g_wqkv_hi[3*CC*CC],     g_wqkv_lo[3*CC*CC];
__device__ __nv_bfloat16 g_wqk_hi [2*CC*CC],     g_wqk_lo [2*CC*CC];
__device__ __nv_bfloat16 g_wproj_hi[CC*CC],      g_wproj_lo[CC*CC];
__device__ __nv_bfloat16 g_wt_hi[(size_t)M2*CC], g_wt_lo[(size_t)M2*CC];
__device__ __nv_bfloat16 g_fin_hi[(size_t)M3*CC],g_fin_lo[(size_t)M3*CC];

// ---------------- PTX helpers (baseline ISA only) ----------------
__device__ __forceinline__ uint32_t smem_u32(const void* p) {
    uint32_t r;
    asm("{ .reg .u64 t; cvta.to.shared.u64 t, %1; cvt.u32.u64 %0, t; }" : "=r"(r) : "l"(p));
    return r;
}
__device__ __forceinline__ void cpa16(uint32_t s, const void* g) {
    asm volatile("cp.async.cg.shared.global [%0], [%1], 16;" :: "r"(s), "l"(g));
}
__device__ __forceinline__ void cpa_commit() {
    asm volatile("cp.async.commit_group;" ::: "memory");
}
template<int N>
__device__ __forceinline__ void cpa_wait() {
    asm volatile("cp.async.wait_group %0;" :: "n"(N) : "memory");
}
__device__ __forceinline__ void ldsm_x4(uint32_t& r0, uint32_t& r1, uint32_t& r2, uint32_t& r3,
                                        uint32_t a) {
    asm volatile("ldmatrix.sync.aligned.m8n8.x4.shared.b16 {%0,%1,%2,%3}, [%4];"
                 : "=r"(r0), "=r"(r1), "=r"(r2), "=r"(r3) : "r"(a));
}
__device__ __forceinline__ void ldsm_x2(uint32_t& r0, uint32_t& r1, uint32_t a) {
    asm volatile("ldmatrix.sync.aligned.m8n8.x2.shared.b16 {%0,%1}, [%2];"
                 : "=r"(r0), "=r"(r1) : "r"(a));
}
__device__ __forceinline__ void mma_bf16(float* d, const uint32_t* a, const uint32_t* b) {
    asm volatile(
        "mma.sync.aligned.m16n8k16.row.col.f32.bf16.bf16.f32 "
        "{%0,%1,%2,%3}, {%4,%5,%6,%7}, {%8,%9}, {%0,%1,%2,%3};"
        : "+f"(d[0]), "+f"(d[1]), "+f"(d[2]), "+f"(d[3])
        : "r"(a[0]), "r"(a[1]), "r"(a[2]), "r"(a[3]), "r"(b[0]), "r"(b[1]));
}

// ---------------- bf16 hi/lo split ----------------
__global__ void split_kernel(const float4* __restrict__ in,
                             __nv_bfloat16* __restrict__ hi,
                             __nv_bfloat16* __restrict__ lo, int n4)
{
    int i = blockIdx.x * 256 + threadIdx.x;
    if (i >= n4) return;
    float4 v = in[i];
    float xs[4] = {v.x, v.y, v.z, v.w};
    union { __nv_bfloat16 b[4]; uint2 u; } H, L;
    #pragma unroll
    for (int j = 0; j < 4; j++) {
        __nv_bfloat16 h = __float2bfloat16(xs[j]);
        H.b[j] = h;
        L.b[j] = __float2bfloat16(xs[j] - __bfloat162float(h));
    }
    *reinterpret_cast<uint2*>(hi + (size_t)i * 4) = H.u;
    *reinterpret_cast<uint2*>(lo + (size_t)i * 4) = L.u;
}

// ---------------- bf16x3 HMMA GEMM ----------------
// 128x128x32 CTA tile, 8 warps (2m x 4n), cp.async double buffer.
// __launch_bounds__(256,2): 2 CTAs/SM (smem 2x80KB, regs forced <=128) so one
// CTA's MMA phase overlaps the other's loads + barrier drain.
#define BKH   32
#define PITCH 80
#define PLANE (128 * PITCH)
#define BUF_B (4 * PLANE)
#define SMEM_TOT (2 * BUF_B)

__device__ __forceinline__ void load_plane(uint32_t dst, const __nv_bfloat16* __restrict__ G,
                                           int row0, int k0, int K, int tid)
{
    #pragma unroll
    for (int i = 0; i < 2; i++) {
        int seg = tid + i * 256;
        int r = seg >> 2, u = seg & 3;
        cpa16(dst + r * PITCH + u * 16, G + (size_t)(row0 + r) * K + k0 + u * 8);
    }
}

__global__ void __launch_bounds__(256, 2)
mma_gemm(const __nv_bfloat16* __restrict__ Ahi, const __nv_bfloat16* __restrict__ Alo,
         const __nv_bfloat16* __restrict__ Bhi, const __nv_bfloat16* __restrict__ Blo,
         const float* __restrict__ bias, float* __restrict__ C, int N, int K)
{
    extern __shared__ __align__(128) char dsm[];
    const int tid  = threadIdx.x;
    const int lane = tid & 31;
    const int wid  = tid >> 5;
    const int wm   = wid & 1;
    const int wn   = wid >> 1;
    const int m0 = blockIdx.y * 128;
    const int n0 = blockIdx.x * 128;
    const uint32_t sb = smem_u32(dsm);

    float acc[4][4][4];
    #pragma unroll
    for (int mi = 0; mi < 4; mi++)
        #pragma unroll
        for (int ni = 0; ni < 4; ni++)
            #pragma unroll
            for (int f = 0; f < 4; f++) acc[mi][ni][f] = 0.f;

    const int NC = K / BKH;

    {
        uint32_t buf = sb;
        load_plane(buf + 0 * PLANE, Ahi, m0, 0, K, tid);
        load_plane(buf + 1 * PLANE, Alo, m0, 0, K, tid);
        load_plane(buf + 2 * PLANE, Bhi, n0, 0, K, tid);
        load_plane(buf + 3 * PLANE, Blo, n0, 0, K, tid);
        cpa_commit();
    }

    const int l16 = lane & 15;
    const uint32_t a_row = wm * 64 + l16;
    const uint32_t a_cb  = ((lane >> 4) & 1) * 16;
    const uint32_t b_row = wn * 32 + (l16 & 7);
    const uint32_t b_cb  = (l16 >> 3) * 16;

    for (int c = 0; c < NC; c++) {
        if (c + 1 < NC) {
            uint32_t buf = sb + ((c + 1) & 1) * BUF_B;
            load_plane(buf + 0 * PLANE, Ahi, m0, (c + 1) * BKH, K, tid);
            load_plane(buf + 1 * PLANE, Alo, m0, (c + 1) * BKH, K, tid);
            load_plane(buf + 2 * PLANE, Bhi, n0, (c + 1) * BKH, K, tid);
            load_plane(buf + 3 * PLANE, Blo, n0, (c + 1) * BKH, K, tid);
            cpa_commit();
            cpa_wait<1>();
        } else {
            cpa_wait<0>();
        }
        __syncthreads();

        const uint32_t buf = sb + (c & 1) * BUF_B;
        #pragma unroll
        for (int ks = 0; ks < 2; ks++) {
            uint32_t ah[4][4], al[4][4], bh[4][2], bl[4][2];
            #pragma unroll
            for (int mi = 0; mi < 4; mi++) {
                uint32_t off = (a_row + mi * 16) * PITCH + ks * 32 + a_cb;
                ldsm_x4(ah[mi][0], ah[mi][1], ah[mi][2], ah[mi][3], buf + 0 * PLANE + off);
                ldsm_x4(al[mi][0], al[mi][1], al[mi][2], al[mi][3], buf + 1 * PLANE + off);
            }
            #pragma unroll
            for (int ni = 0; ni < 4; ni++) {
                uint32_t off = (b_row + ni * 8) * PITCH + ks * 32 + b_cb;
                ldsm_x2(bh[ni][0], bh[ni][1], buf + 2 * PLANE + off);
                ldsm_x2(bl[ni][0], bl[ni][1], buf + 3 * PLANE + off);
            }
            #pragma unroll
            for (int mi = 0; mi < 4; mi++)
                #pragma unroll
                for (int ni = 0; ni < 4; ni++) {
                    mma_bf16(acc[mi][ni], ah[mi], bh[ni]);
                    mma_bf16(acc[mi][ni], ah[mi], bl[ni]);
                    mma_bf16(acc[mi][ni], al[mi], bh[ni]);
                }
        }
        __syncthreads();
    }

    const int rr = lane >> 2, cp = (lane & 3) * 2;
    #pragma unroll
    for (int mi = 0; mi < 4; mi++) {
        int row = m0 + wm * 64 + mi * 16 + rr;
        #pragma unroll
        for (int ni = 0; ni < 4; ni++) {
            int col = n0 + wn * 32 + ni * 8 + cp;
            float b0 = 0.f, b1 = 0.f;
            if (bias) { b0 = bias[col]; b1 = bias[col + 1]; }
            float* p = C + (size_t)row * N + col;
            p[0] = acc[mi][ni][0] + b0;
            p[1] = acc[mi][ni][1] + b1;
            float* q = p + (size_t)8 * N;
            q[0] = acc[mi][ni][2] + b0;
            q[1] = acc[mi][ni][3] + b1;
        }
    }
}

// ---------------- K2: per-(window, head) attention + residual (R3 best) -----
__global__ void win_attn_kernel(const float* __restrict__ qkv,
                                const float* __restrict__ x,
                                float* __restrict__ out1)
{
    const int bw = blockIdx.x;
    const int hh = blockIdx.y;
    __shared__ float q[NT][32];
    __shared__ float k[NT][33];
    __shared__ float v[NT][32];
    __shared__ float at[NT][NT];
    const int tid = threadIdx.x; // 256

    const float* base = qkv + (size_t)bw * NT * (3 * CC) + hh * DD;
    for (int idx = tid; idx < NT * 32; idx += 256) {
        int i = idx >> 5, dd = idx & 31;
        const float* row = base + (size_t)i * (3 * CC);
        q[i][dd] = row[dd];
        k[i][dd] = row[CC + dd];
        v[i][dd] = row[2 * CC + dd];
    }
    __syncthreads();

    for (int idx = tid; idx < NT * NT; idx += 256) {
        int i = idx / NT, j = idx % NT;
        float s = 0.f;
        #pragma unroll
        for (int d = 0; d < 32; d++) s += q[i][d] * k[j][d];
        at[i][j] = s * SCALE;
    }
    __syncthreads();

    if (tid < NT) {
        float m = -1e30f;
        for (int j = 0; j < NT; j++) m = fmaxf(m, at[tid][j]);
        float sum = 0.f;
        for (int j = 0; j < NT; j++) { float e = __expf(at[tid][j] - m); at[tid][j] = e; sum += e; }
        float inv = 1.f / sum;
        for (int j = 0; j < NT; j++) at[tid][j] *= inv;
    }
    __syncthreads();

    for (int idx = tid; idx < NT * 32; idx += 256) {
        int i = idx >> 5, dd = idx & 31;
        float s = 0.f;
        #pragma unroll 10
        for (int j = 0; j < NT; j++) s += at[i][j] * v[j][dd];
        size_t o = (size_t)bw * NT * CC + (size_t)i * CC + hh * DD + dd;
        out1[o] = s + x[o];
    }
}

// ---------------- K3a: LayerNorm + exact GELU -> bf16 hi/lo -----------------
__global__ void ln_gelu_kernel(const float* __restrict__ out1,
                               const float* __restrict__ g,
                               const float* __restrict__ b,
                               __nv_bfloat16* __restrict__ wt_hi,
                               __nv_bfloat16* __restrict__ wt_lo)
{
    const int bw = blockIdx.x;
    const int tid = threadIdx.x; // 128
    const float* row = out1 + (size_t)bw * NT * CC;
    float vv[3], s = 0.f, s2 = 0.f;
    #pragma unroll
    for (int i = 0; i < 3; i++) {
        vv[i] = row[tid + i * 128];
        s += vv[i]; s2 += vv[i] * vv[i];
    }
    __shared__ float rs[4], rs2[4];
    #pragma unroll
    for (int o = 16; o; o >>= 1) {
        s  += __shfl_down_sync(0xFFFFFFFFu, s,  o);
        s2 += __shfl_down_sync(0xFFFFFFFFu, s2, o);
    }
    if ((tid & 31) == 0) { rs[tid >> 5] = s; rs2[tid >> 5] = s2; }
    __syncthreads();
    float S  = rs[0] + rs[1] + rs[2] + rs[3];
    float S2 = rs2[0] + rs2[1] + rs2[2] + rs2[3];
    float mean = S / (float)CC;
    float var  = S2 / (float)CC - mean * mean;
    float inv  = rsqrtf(var + 1e-5f);
    #pragma unroll
    for (int i = 0; i < 3; i++) {
        int c = tid + i * 128;
        float nz = (vv[i] - mean) * inv * g[c] + b[c];
        float ge = 0.5f * nz * (1.f + erff(nz * 0.70710678118654752f));
        __nv_bfloat16 h = __float2bfloat16(ge);
        wt_hi[(size_t)bw * CC + c] = h;
        wt_lo[(size_t)bw * CC + c] = __float2bfloat16(ge - __bfloat162float(h));
    }
}

// ---------------- K4: pooled attention softmax ------------------------------
__global__ void pool_attn_kernel(const float* __restrict__ pqk,
                                 float* __restrict__ pattn)
{
    const int b = blockIdx.x, hh = blockIdx.y;
    __shared__ float pq[WN][32];
    __shared__ float pk[WN][33];
    __shared__ float sc[WN][WN];
    const int tid = threadIdx.x; // 256

    for (int idx = tid; idx < WN * 32; idx += 256) {
        int w = idx >> 5, d = idx & 31;
        size_t base = (size_t)(b * WN + w) * (2 * CC) + hh * DD + d;
        pq[w][d] = pqk[base];
        pk[w][d] = pqk[base + CC];
    }
    __syncthreads();

    for (int idx = tid; idx < WN * WN; idx += 256) {
        int w = idx >> 6, vv = idx & 63;
        float s = 0.f;
        #pragma unroll
        for (int d = 0; d < 32; d++) s += pq[w][d] * pk[vv][d];
        sc[w][vv] = s * SCALE;
    }
    __syncthreads();

    if (tid < WN) {
        float m = -1e30f;
        for (int j = 0; j < WN; j++) m = fmaxf(m, sc[tid][j]);
        float sum = 0.f;
        for (int j = 0; j < WN; j++) { float e = __expf(sc[tid][j] - m); sc[tid][j] = e; sum += e; }
        float inv = 1.f / sum;
        for (int j = 0; j < WN; j++) sc[tid][j] *= inv;
    }
    __syncthreads();

    float* dst = pattn + (size_t)(b * NH + hh) * WN * WN;
    for (int idx = tid; idx < WN * WN; idx += 256) dst[idx] = sc[idx >> 6][idx & 63];
}

// ---------------- K5: PSA mix + residual + rearrange -> bf16 hi/lo (R3 best) -
__global__ void psa_kernel(const float* __restrict__ pattn,
                           const float* __restrict__ out1,
                           __nv_bfloat16* __restrict__ fin_hi,
                           __nv_bfloat16* __restrict__ fin_lo)
{
    const int bh = blockIdx.x;
    const int b = bh / NH, hh = bh % NH;
    const int si = blockIdx.y;
    __shared__ float sp[WN][WN];
    const int tid = threadIdx.x; // 224

    const float* src = pattn + (size_t)bh * WN * WN;
    for (int idx = tid; idx < WN * WN; idx += 224) sp[idx >> 6][idx & 63] = src[idx];
    __syncthreads();

    const int sj = tid >> 5, dd = tid & 31;
    const int s = si * 7 + sj;
    const int col = hh * DD + dd;

    float acc[WN];
    #pragma unroll
    for (int w = 0; w < WN; w++) acc[w] = 0.f;

    for (int vv = 0; vv < WN; vv++) {
        float bv = out1[((size_t)(b * WN + vv) * NT + s + 1) * CC + col];
        #pragma unroll
        for (int w = 0; w < WN; w++) acc[w] += sp[w][vv] * bv;
    }

    for (int w = 0; w < WN; w++) {
        float ax = out1[((size_t)(b * WN + w) * NT + s + 1) * CC + col];
        int hi = w >> 3, wi = w & 7;
        int y = hi * WS + si, xx = wi * WS + sj;
        size_t o = ((size_t)b * HW + y * 56 + xx) * CC + col;
        float f = acc[w] + ax;
        __nv_bfloat16 h = __float2bfloat16(f);
        fin_hi[o] = h;
        fin_lo[o] = __float2bfloat16(f - __bfloat162float(h));
    }
}

// ---------------- launch ----------------
extern "C" void kernel_launch(void* const* d_in, const int* in_sizes, int n_in,
                              void* d_out, int out_size)
{
    const float* x      = (const float*)d_in[0];
    const float* w_qkv  = (const float*)d_in[3];
    const float* w_qk   = (const float*)d_in[4];
    const float* ln_g   = (const float*)d_in[5];
    const float* ln_b   = (const float*)d_in[6];
    const float* w_proj = (const float*)d_in[7];
    const float* b_proj = (const float*)d_in[8];
    float* out = (float*)d_out;

    float *p_qkv, *p_out1, *p_pqk, *p_pattn;
    __nv_bfloat16 *p_xh, *p_xl, *p_wqkvh, *p_wqkvl, *p_wqkh, *p_wqkl,
                  *p_wprojh, *p_wprojl, *p_wth, *p_wtl, *p_finh, *p_finl;
    cudaGetSymbolAddress((void**)&p_qkv,   g_qkv);
    cudaGetSymbolAddress((void**)&p_out1,  g_out1);
    cudaGetSymbolAddress((void**)&p_pqk,   g_pqk);
    cudaGetSymbolAddress((void**)&p_pattn, g_pattn);
    cudaGetSymbolAddress((void**)&p_xh,    g_x_hi);
    cudaGetSymbolAddress((void**)&p_xl,    g_x_lo);
    cudaGetSymbolAddress((void**)&p_wqkvh, g_wqkv_hi);
    cudaGetSymbolAddress((void**)&p_wqkvl, g_wqkv_lo);
    cudaGetSymbolAddress((void**)&p_wqkh,  g_wqk_hi);
    cudaGetSymbolAddress((void**)&p_wqkl,  g_wqk_lo);
    cudaGetSymbolAddress((void**)&p_wprojh,g_wproj_hi);
    cudaGetSymbolAddress((void**)&p_wprojl,g_wproj_lo);
    cudaGetSymbolAddress((void**)&p_wth,   g_wt_hi);
    cudaGetSymbolAddress((void**)&p_wtl,   g_wt_lo);
    cudaGetSymbolAddress((void**)&p_finh,  g_fin_hi);
    cudaGetSymbolAddress((void**)&p_finl,  g_fin_lo);

    cudaFuncSetAttribute(mma_gemm, cudaFuncAttributeMaxDynamicSharedMemorySize, SMEM_TOT);

    // splits
    {
        int n4 = (M1 * CC) / 4;
        split_kernel<<<(n4 + 255) / 256, 256>>>((const float4*)x, p_xh, p_xl, n4);
        n4 = (3 * CC * CC) / 4;
        split_kernel<<<(n4 + 255) / 256, 256>>>((const float4*)w_qkv, p_wqkvh, p_wqkvl, n4);
        n4 = (2 * CC * CC) / 4;
        split_kernel<<<(n4 + 255) / 256, 256>>>((const float4*)w_qk, p_wqkh, p_wqkl, n4);
        n4 = (CC * CC) / 4;
        split_kernel<<<(n4 + 255) / 256, 256>>>((const float4*)w_proj, p_wprojh, p_wprojl, n4);
    }

    // K1: qkv = x @ w_qkv^T  (102400 x 1152, K=384)
    mma_gemm<<<dim3(3 * CC / 128, M1 / 128), 256, SMEM_TOT>>>(
        p_xh, p_xl, p_wqkvh, p_wqkvl, nullptr, p_qkv, 3 * CC, CC);

    // K2: window attention + residual
    win_attn_kernel<<<dim3(BB * WN, NH), 256>>>(p_qkv, x, p_out1);

    // K3a: LN + GELU -> bf16 hi/lo
    ln_gelu_kernel<<<M2, 128>>>(p_out1, ln_g, ln_b, p_wth, p_wtl);

    // K3b: pqk = wintok @ w_qk^T  (2048 x 768, K=384)
    mma_gemm<<<dim3(2 * CC / 128, M2 / 128), 256, SMEM_TOT>>>(
        p_wth, p_wtl, p_wqkh, p_wqkl, nullptr, p_pqk, 2 * CC, CC);

    // K4: pooled attention softmax
    pool_attn_kernel<<<dim3(BB, NH), 256>>>(p_pqk, p_pattn);

    // K5: PSA mix + residual + rearrange -> bf16 hi/lo
    psa_kernel<<<dim3(BB * NH, WS), 224>>>(p_pattn, p_out1, p_finh, p_finl);

    // K6: out = final @ w_proj^T + b_proj  (100352 x 384, K=384)
    mma_gemm<<<dim3(CC / 128, M3 / 128), 256, SMEM_TOT>>>(
        p_finh, p_finl, p_wprojh, p_wprojl, b_proj, out, CC, CC);
}